// round 14
// baseline (speedup 1.0000x reference)
#include <cuda_runtime.h>

typedef unsigned long long u64;
typedef unsigned int u32;

#define NB 2
#define NH 12
#define SQ 1024
#define DK 64
#define DM 768

// ---------------- scratch ----------------
__device__ float g_q[NB*NH*SQ*DK];                 // pre-scaled by 1/64
__device__ float g_k[NB*NH*SQ*DK];
__device__ float g_v[NB*NH*SQ*DK];
__device__ float g_scores[(size_t)NB*NH*SQ*SQ];    // scores, then probs (in place)
__device__ float g_attn[NB*SQ*DM];                 // w_rel
__device__ float g_attn2[NB*SQ*DM];                // wv partial (k 0..511)
__device__ float g_attn3[NB*SQ*DM];                // wv partial (k 512..1023)

// ---------------- tf32 mma helpers ----------------
__device__ __forceinline__ u32 to_tf32(float f){
    u32 u; asm("cvt.rna.tf32.f32 %0, %1;" : "=r"(u) : "f"(f)); return u;
}
__device__ __forceinline__ uint4 cvt4(float4 v){
    uint4 u; u.x = to_tf32(v.x); u.y = to_tf32(v.y); u.z = to_tf32(v.z); u.w = to_tf32(v.w);
    return u;
}
__device__ __forceinline__ void mma_tf32(float* c, const u32* a, const u32* b){
    asm volatile(
        "mma.sync.aligned.m16n8k8.row.col.f32.tf32.tf32.f32 "
        "{%0,%1,%2,%3}, {%4,%5,%6,%7}, {%8,%9}, {%0,%1,%2,%3};"
        : "+f"(c[0]), "+f"(c[1]), "+f"(c[2]), "+f"(c[3])
        : "r"(a[0]), "r"(a[1]), "r"(a[2]), "r"(a[3]), "r"(b[0]), "r"(b[1]));
}

// ---------------- L2 cache-policy helpers (createpolicy + cache_hint) ----------------
__device__ __forceinline__ u64 pol_evict_first(){
    u64 p; asm("createpolicy.fractional.L2::evict_first.b64 %0, 1.0;" : "=l"(p));
    return p;
}
__device__ __forceinline__ u64 pol_evict_last(){
    u64 p; asm("createpolicy.fractional.L2::evict_last.b64 %0, 1.0;" : "=l"(p));
    return p;
}
__device__ __forceinline__ float4 ldg_pol4(const float* p, u64 pol){
    float4 v;
    asm("ld.global.L2::cache_hint.v4.f32 {%0,%1,%2,%3}, [%4], %5;"
        : "=f"(v.x), "=f"(v.y), "=f"(v.z), "=f"(v.w) : "l"(p), "l"(pol));
    return v;
}
__device__ __forceinline__ void stg_pol4(float* p, float4 v, u64 pol){
    asm volatile("st.global.L2::cache_hint.v4.f32 [%0], {%1,%2,%3,%4}, %5;"
        :: "l"(p), "f"(v.x), "f"(v.y), "f"(v.z), "f"(v.w), "l"(pol) : "memory");
}
__device__ __forceinline__ void stg_pol2(float* p, float2 v, u64 pol){
    asm volatile("st.global.L2::cache_hint.v2.f32 [%0], {%1,%2}, %3;"
        :: "l"(p), "f"(v.x), "f"(v.y), "l"(pol) : "memory");
}

// =====================================================================
// K1: QKV projections via tf32 mma with split-A (2 mma) for accuracy.
// grid (16, 12, 3).
// =====================================================================
__global__ __launch_bounds__(256) void k_proj(
    const float* __restrict__ Xq, const float* __restrict__ Xk, const float* __restrict__ Xv,
    const float* __restrict__ Wq, const float* __restrict__ Wk, const float* __restrict__ Wv,
    const float* __restrict__ bq, const float* __restrict__ bk, const float* __restrict__ bv)
{
    const int z = blockIdx.z;
    const float* X    = (z == 0) ? Xq : (z == 1) ? Xk : Xv;
    const float* W    = (z == 0) ? Wq : (z == 1) ? Wk : Wv;
    const float* bias = (z == 0) ? bq : (z == 1) ? bk : bv;
    float* out        = (z == 0) ? g_q : (z == 1) ? g_k : g_v;
    const float scale = (z == 0) ? (1.0f / 64.0f) : 1.0f;

    __shared__ __align__(16) u32 Ah[128][36];
    __shared__ __align__(16) u32 Al[128][36];
    __shared__ __align__(16) u32 Bs[32][72];

    const int tid = threadIdx.x;
    const int lane = tid & 31;
    const int warp = tid >> 5;
    const int wm = warp >> 1;
    const int wn = warp & 1;
    const int rq = lane >> 2;
    const int cq = lane & 3;
    const int m0 = blockIdx.x * 128;
    const int h  = blockIdx.y;
    const int n0 = h * 64;

    float acc[2][4][4];
    #pragma unroll
    for (int i = 0; i < 2; i++)
        #pragma unroll
        for (int j = 0; j < 4; j++)
            #pragma unroll
            for (int t = 0; t < 4; t++) acc[i][j][t] = 0.f;

    float4 pfa[4], pfb[2];
    #pragma unroll
    for (int it = 0; it < 4; it++) {
        int f = tid + it * 256;
        pfa[it] = *(const float4*)(X + (size_t)(m0 + (f >> 3)) * DM + (f & 7) * 4);
    }
    #pragma unroll
    for (int it = 0; it < 2; it++) {
        int f = tid + it * 256;
        pfb[it] = *(const float4*)(W + (size_t)(f >> 4) * DM + n0 + (f & 15) * 4);
    }

    for (int k0 = 0; k0 < DM; k0 += 32) {
        __syncthreads();
        #pragma unroll
        for (int it = 0; it < 4; it++) {
            int f = tid + it * 256;
            int m = f >> 3;
            int k4 = (f & 7) * 4;
            float4 v = pfa[it];
            uint4 hi = cvt4(v);
            float4 r;
            r.x = v.x - __uint_as_float(hi.x);
            r.y = v.y - __uint_as_float(hi.y);
            r.z = v.z - __uint_as_float(hi.z);
            r.w = v.w - __uint_as_float(hi.w);
            *(uint4*)&Ah[m][k4] = hi;
            *(uint4*)&Al[m][k4] = cvt4(r);
        }
        #pragma unroll
        for (int it = 0; it < 2; it++) {
            int f = tid + it * 256;
            *(uint4*)&Bs[f >> 4][(f & 15) * 4] = cvt4(pfb[it]);
        }
        __syncthreads();

        if (k0 + 32 < DM) {
            #pragma unroll
            for (int it = 0; it < 4; it++) {
                int f = tid + it * 256;
                pfa[it] = *(const float4*)(X + (size_t)(m0 + (f >> 3)) * DM + k0 + 32 + (f & 7) * 4);
            }
            #pragma unroll
            for (int it = 0; it < 2; it++) {
                int f = tid + it * 256;
                pfb[it] = *(const float4*)(W + (size_t)(k0 + 32 + (f >> 4)) * DM + n0 + (f & 15) * 4);
            }
        }

        #pragma unroll
        for (int ks = 0; ks < 4; ks++) {
            int kk = ks * 8;
            u32 ah[2][4], al[2][4], bf[4][2];
            #pragma unroll
            for (int mi = 0; mi < 2; mi++) {
                int r = wm * 32 + mi * 16 + rq;
                ah[mi][0] = Ah[r][kk + cq];
                ah[mi][1] = Ah[r + 8][kk + cq];
                ah[mi][2] = Ah[r][kk + cq + 4];
                ah[mi][3] = Ah[r + 8][kk + cq + 4];
                al[mi][0] = Al[r][kk + cq];
                al[mi][1] = Al[r + 8][kk + cq];
                al[mi][2] = Al[r][kk + cq + 4];
                al[mi][3] = Al[r + 8][kk + cq + 4];
            }
            #pragma unroll
            for (int ni = 0; ni < 4; ni++) {
                int n = wn * 32 + ni * 8 + rq;
                bf[ni][0] = Bs[kk + cq][n];
                bf[ni][1] = Bs[kk + cq + 4][n];
            }
            #pragma unroll
            for (int mi = 0; mi < 2; mi++)
                #pragma unroll
                for (int ni = 0; ni < 4; ni++) {
                    mma_tf32(acc[mi][ni], ah[mi], bf[ni]);
                    mma_tf32(acc[mi][ni], al[mi], bf[ni]);
                }
        }
    }

    #pragma unroll
    for (int mi = 0; mi < 2; mi++) {
        #pragma unroll
        for (int ni = 0; ni < 4; ni++) {
            int ncol = wn * 32 + ni * 8 + cq * 2;
            float bx = bias[n0 + ncol];
            float by = bias[n0 + ncol + 1];
            int m = m0 + wm * 32 + mi * 16 + rq;
            {
                int b = m >> 10, s = m & (SQ - 1);
                float* dst = out + ((size_t)((b * NH + h) * SQ + s)) * DK + ncol;
                *(float2*)dst = make_float2((acc[mi][ni][0] + bx) * scale,
                                            (acc[mi][ni][1] + by) * scale);
            }
            {
                int m2 = m + 8;
                int b = m2 >> 10, s = m2 & (SQ - 1);
                float* dst = out + ((size_t)((b * NH + h) * SQ + s)) * DK + ncol;
                *(float2*)dst = make_float2((acc[mi][ni][2] + bx) * scale,
                                            (acc[mi][ni][3] + by) * scale);
            }
        }
    }
}

// =====================================================================
// K2: scores = q @ k^T per (b,h) via tf32 mma. Score stores evict_last.
// grid (8, 8, 24), dyn smem 69632 B.
// =====================================================================
__global__ __launch_bounds__(256) void k_qk()
{
    extern __shared__ __align__(16) u32 smu[];
    u32 (*Qs)[68] = (u32(*)[68])smu;
    u32 (*Ks)[68] = (u32(*)[68])(smu + 128 * 68);

    const u64 pel = pol_evict_last();

    const int bh = blockIdx.z;
    const float* Aq = g_q + (size_t)bh * SQ * DK;
    const float* Bk = g_k + (size_t)bh * SQ * DK;
    float* C = g_scores + (size_t)bh * SQ * SQ;

    const int m0 = blockIdx.x * 128;
    const int n0 = blockIdx.y * 128;
    const int tid = threadIdx.x;
    const int lane = tid & 31;
    const int warp = tid >> 5;
    const int wm = warp >> 2;
    const int wn = warp & 3;
    const int rq = lane >> 2;
    const int cq = lane & 3;

    #pragma unroll
    for (int it = 0; it < 8; it++) {
        int f = tid + it * 256;
        int r  = f >> 4;
        int d4 = (f & 15) * 4;
        float4 va = *(const float4*)(Aq + (size_t)(m0 + r) * DK + d4);
        float4 vb = *(const float4*)(Bk + (size_t)(n0 + r) * DK + d4);
        *(uint4*)&Qs[r][d4] = cvt4(va);
        *(uint4*)&Ks[r][d4] = cvt4(vb);
    }
    __syncthreads();

    float acc[4][4][4];
    #pragma unroll
    for (int i = 0; i < 4; i++)
        #pragma unroll
        for (int j = 0; j < 4; j++)
            #pragma unroll
            for (int t = 0; t < 4; t++) acc[i][j][t] = 0.f;

    #pragma unroll
    for (int ks = 0; ks < 8; ks++) {
        int d0 = ks * 8;
        u32 a[4][4], bf[4][2];
        #pragma unroll
        for (int mi = 0; mi < 4; mi++) {
            int r = wm * 64 + mi * 16 + rq;
            a[mi][0] = Qs[r][d0 + cq];
            a[mi][1] = Qs[r + 8][d0 + cq];
            a[mi][2] = Qs[r][d0 + cq + 4];
            a[mi][3] = Qs[r + 8][d0 + cq + 4];
        }
        #pragma unroll
        for (int ni = 0; ni < 4; ni++) {
            int n = wn * 32 + ni * 8 + rq;
            bf[ni][0] = Ks[n][d0 + cq];
            bf[ni][1] = Ks[n][d0 + cq + 4];
        }
        #pragma unroll
        for (int mi = 0; mi < 4; mi++)
            #pragma unroll
            for (int ni = 0; ni < 4; ni++)
                mma_tf32(acc[mi][ni], a[mi], bf[ni]);
    }

    #pragma unroll
    for (int mi = 0; mi < 4; mi++) {
        #pragma unroll
        for (int ni = 0; ni < 4; ni++) {
            int r0 = m0 + wm * 64 + mi * 16 + rq;
            int c0 = n0 + wn * 32 + ni * 8 + cq * 2;
            stg_pol2(C + (size_t)r0 * SQ + c0,
                     make_float2(acc[mi][ni][0], acc[mi][ni][1]), pel);
            stg_pol2(C + (size_t)(r0 + 8) * SQ + c0,
                     make_float2(acc[mi][ni][2], acc[mi][ni][3]), pel);
        }
    }
}

// =====================================================================
// K3 (fused): per (b,q): scores += q . relation_k (tf32 mma), softmax.
// relK loads evict_first; score loads evict_first; prob stores evict_last.
// 512 threads. grid (1024, 2), dyn smem 88064 B.
// =====================================================================
__global__ __launch_bounds__(512) void k_qrel_sm(const float* __restrict__ relk)
{
    extern __shared__ __align__(16) float sm[];
    float* ss = sm;                                        // 12*1024 floats
    u32 (*rks)[68] = (u32(*)[68])(sm + NH * SQ);           // 128*68 tf32
    u32 (*qs)[64] = (u32(*)[64])(sm + NH * SQ + 128 * 68); // 16*64 tf32 (rows 12-15 zero)

    const u64 pef = pol_evict_first();
    const u64 pel = pol_evict_last();

    const int b = blockIdx.y, q = blockIdx.x;
    const int tid = threadIdx.x;
    const int lane = tid & 31;
    const int warp = tid >> 5;       // 0..15
    const int rq = lane >> 2;        // 0..7
    const int cq = lane & 3;         // 0..3
    const int n0c = warp * 8;

    if (tid < 192) {
        int hh = tid >> 4;
        int d4 = (tid & 15) * 4;
        float4 v = *(const float4*)(g_q + ((size_t)((b * NH + hh) * SQ + q)) * DK + d4);
        *(uint4*)&qs[hh][d4] = cvt4(v);
    } else if (tid < 256) {
        int r = 12 + ((tid - 192) >> 4);
        int d4 = ((tid - 192) & 15) * 4;
        *(uint4*)&qs[r][d4] = make_uint4(0u, 0u, 0u, 0u);
    }
    #pragma unroll
    for (int it = 0; it < 6; it++) {
        int f = tid + it * 512;
        int hh = f >> 8;
        int k4 = (f & 255) * 4;
        *(float4*)&ss[hh * SQ + k4] =
            ldg_pol4(g_scores + ((size_t)((b * NH + hh) * SQ + q)) * SQ + k4, pef);
    }

    const float* relbase = relk + ((size_t)(b * SQ + q)) * SQ * DK;

    float4 pf[4];
    #pragma unroll
    for (int it = 0; it < 4; it++) {
        int f = tid + it * 512;
        pf[it] = ldg_pol4(relbase + (size_t)(f >> 4) * DK + (f & 15) * 4, pef);
    }
    __syncthreads();

    u32 afrag[8][4];
    #pragma unroll
    for (int ks = 0; ks < 8; ks++) {
        int d0 = ks * 8;
        afrag[ks][0] = qs[rq][d0 + cq];
        afrag[ks][1] = qs[rq + 8][d0 + cq];
        afrag[ks][2] = qs[rq][d0 + cq + 4];
        afrag[ks][3] = qs[rq + 8][d0 + cq + 4];
    }

    for (int kt = 0; kt < SQ; kt += 128) {
        __syncthreads();
        #pragma unroll
        for (int it = 0; it < 4; it++) {
            int f = tid + it * 512;
            *(uint4*)&rks[f >> 4][(f & 15) * 4] = cvt4(pf[it]);
        }
        __syncthreads();

        if (kt + 128 < SQ) {
            #pragma unroll
            for (int it = 0; it < 4; it++) {
                int f = tid + it * 512;
                pf[it] = ldg_pol4(relbase + (size_t)(kt + 128 + (f >> 4)) * DK + (f & 15) * 4, pef);
            }
        }

        float acc[4] = {0.f, 0.f, 0.f, 0.f};
        #pragma unroll
        for (int ks = 0; ks < 8; ks++) {
            int d0 = ks * 8;
            u32 bf[2];
            bf[0] = rks[n0c + rq][d0 + cq];
            bf[1] = rks[n0c + rq][d0 + cq + 4];
            mma_tf32(acc, afrag[ks], bf);
        }

        int col = kt + n0c + cq * 2;
        ss[rq * SQ + col]     += acc[0];
        ss[rq * SQ + col + 1] += acc[1];
        if (rq < 4) {
            ss[(rq + 8) * SQ + col]     += acc[2];
            ss[(rq + 8) * SQ + col + 1] += acc[3];
        }
    }
    __syncthreads();

    const int swarp = tid >> 5;
    const int slane = tid & 31;
    if (swarp < NH) {
        float* p = ss + swarp * SQ;
        float4 v[8];
        float mx = -3.4e38f;
        #pragma unroll
        for (int j = 0; j < 8; j++) {
            v[j] = *(float4*)(p + slane * 4 + j * 128);
            mx = fmaxf(mx, fmaxf(fmaxf(v[j].x, v[j].y), fmaxf(v[j].z, v[j].w)));
        }
        #pragma unroll
        for (int o = 16; o > 0; o >>= 1) mx = fmaxf(mx, __shfl_xor_sync(0xffffffffu, mx, o));

        float s = 0.f;
        #pragma unroll
        for (int j = 0; j < 8; j++) {
            v[j].x = __expf(v[j].x - mx);
            v[j].y = __expf(v[j].y - mx);
            v[j].z = __expf(v[j].z - mx);
            v[j].w = __expf(v[j].w - mx);
            s += v[j].x + v[j].y + v[j].z + v[j].w;
        }
        #pragma unroll
        for (int o = 16; o > 0; o >>= 1) s += __shfl_xor_sync(0xffffffffu, s, o);
        const float inv = 1.0f / s;

        float* dst = g_scores + ((size_t)((b * NH + swarp) * SQ + q)) * SQ;
        #pragma unroll
        for (int j = 0; j < 8; j++) {
            v[j].x *= inv; v[j].y *= inv; v[j].z *= inv; v[j].w *= inv;
            stg_pol4(dst + slane * 4 + j * 128, v[j], pel);
        }
    }
}

// =====================================================================
// K5+K6 merged (k_pv): single launch, flattened grid of 2432 CTAs.
//   CTAs [0, 2048): w_rel  = probs @ relation_v  -> g_attn
//   CTAs [2048, 2432): wv  = probs @ v (split-K) -> g_attn2/g_attn3
// relV loads evict_first; wrel prob loads evict_last; wv prob loads evict_first.
// 256 threads, dyn smem 45312 B.
// =====================================================================
__global__ __launch_bounds__(256) void k_pv(const float* __restrict__ relv)
{
    extern __shared__ __align__(16) u32 dyn[];

    const int tid = threadIdx.x;
    const int lane = tid & 31;
    const int warp = tid >> 5;
    const int rq = lane >> 2;
    const int cq = lane & 3;

    if (blockIdx.x < 2048) {
        // ---------------- w_rel path ----------------
        u32 (*rvs)[72] = (u32(*)[72])dyn;                 // 128x72
        u32 (*ps)[132] = (u32(*)[132])(dyn + 128 * 72);   // 16x132

        const u64 pef = pol_evict_first();
        const u64 pel = pol_evict_last();

        const int q = blockIdx.x & (SQ - 1);
        const int b = blockIdx.x >> 10;
        const int n0c = warp * 8;

        {
            int r = 12 + (tid >> 6);
            int c = (tid & 63) * 2;
            ps[r][c] = 0u; ps[r][c + 1] = 0u;
        }

        const float* relbase = relv + ((size_t)(b * SQ + q)) * SQ * DK;
        const float* psrc = g_scores + ((size_t)(b * NH) * SQ + q) * SQ;

        float acc[4] = {0.f, 0.f, 0.f, 0.f};

        float4 pfr[8], pfp[2];
        #pragma unroll
        for (int it = 0; it < 8; it++) {
            int f = tid + it * 256;
            pfr[it] = ldg_pol4(relbase + (size_t)(f >> 4) * DK + (f & 15) * 4, pef);
        }
        #pragma unroll
        for (int it = 0; it < 2; it++) {
            int f = tid + it * 256;
            if (f < 384)
                pfp[it] = ldg_pol4(psrc + (size_t)(f >> 5) * SQ * SQ + (f & 31) * 4, pel);
        }

        for (int kt = 0; kt < SQ; kt += 128) {
            __syncthreads();
            #pragma unroll
            for (int it = 0; it < 8; it++) {
                int f = tid + it * 256;
                *(uint4*)&rvs[f >> 4][(f & 15) * 4] = cvt4(pfr[it]);
            }
            #pragma unroll
            for (int it = 0; it < 2; it++) {
                int f = tid + it * 256;
                if (f < 384)
                    *(uint4*)&ps[f >> 5][(f & 31) * 4] = cvt4(pfp[it]);
            }
            __syncthreads();

            if (kt + 128 < SQ) {
                #pragma unroll
                for (int it = 0; it < 8; it++) {
                    int f = tid + it * 256;
                    pfr[it] = ldg_pol4(relbase + (size_t)(kt + 128 + (f >> 4)) * DK + (f & 15) * 4, pef);
                }
                #pragma unroll
                for (int it = 0; it < 2; it++) {
                    int f = tid + it * 256;
                    if (f < 384)
                        pfp[it] = ldg_pol4(psrc + (size_t)(f >> 5) * SQ * SQ + kt + 128 + (f & 31) * 4, pel);
                }
            }

            #pragma unroll
            for (int ks = 0; ks < 16; ks++) {
                int kk = ks * 8;
                u32 a[4], bf[2];
                a[0] = ps[rq][kk + cq];
                a[1] = ps[rq + 8][kk + cq];
                a[2] = ps[rq][kk + cq + 4];
                a[3] = ps[rq + 8][kk + cq + 4];
                bf[0] = rvs[kk + cq][n0c + rq];
                bf[1] = rvs[kk + cq + 4][n0c + rq];
                mma_tf32(acc, a, bf);
            }
        }

        const size_t base = (size_t)(b * SQ + q) * DM;
        const int col = n0c + cq * 2;
        *(float2*)(g_attn + base + rq * DK + col) = make_float2(acc[0], acc[1]);
        if (rq < 4)
            *(float2*)(g_attn + base + (rq + 8) * DK + col) = make_float2(acc[2], acc[3]);
    } else {
        // ---------------- wv path ----------------
        u32 (*As)[36] = (u32(*)[36])dyn;                 // 128x36
        u32 (*Bs)[72] = (u32(*)[72])(dyn + 128 * 36);    // 32x72

        const u64 pef = pol_evict_first();

        const int idx = blockIdx.x - 2048;
        const int m0 = (idx & 7) * 128;
        const int bh = (idx >> 3) % (NB * NH);
        const int kz = idx / (8 * NB * NH);
        const int b = bh / NH, h = bh % NH;
        const int koff = kz * 512;
        const float* A  = g_scores + (size_t)bh * SQ * SQ + koff;
        const float* Bv = g_v + ((size_t)bh * SQ + koff) * DK;
        float* outp = kz ? g_attn3 : g_attn2;

        const int wm = warp >> 1;
        const int wn = warp & 1;

        float acc[2][4][4];
        #pragma unroll
        for (int i = 0; i < 2; i++)
            #pragma unroll
            for (int j = 0; j < 4; j++)
                #pragma unroll
                for (int t = 0; t < 4; t++) acc[i][j][t] = 0.f;

        float4 pfa[4], pfb[2];
        #pragma unroll
        for (int it = 0; it < 4; it++) {
            int f = tid + it * 256;
            pfa[it] = ldg_pol4(A + (size_t)(m0 + (f >> 3)) * SQ + (f & 7) * 4, pef);
        }
        #pragma unroll
        for (int it = 0; it < 2; it++) {
            int f = tid + it * 256;
            pfb[it] = *(const float4*)(Bv + (size_t)(f >> 4) * DK + (f & 15) * 4);
        }

        for (int k0 = 0; k0 < 512; k0 += 32) {
            __syncthreads();
            #pragma unroll
            for (int it = 0; it < 4; it++) {
                int f = tid + it * 256;
                *(uint4*)&As[f >> 3][(f & 7) * 4] = cvt4(pfa[it]);
            }
            #pragma unroll
            for (int it = 0; it < 2; it++) {
                int f = tid + it * 256;
                *(uint4*)&Bs[f >> 4][(f & 15) * 4] = cvt4(pfb[it]);
            }
            __syncthreads();

            if (k0 + 32 < 512) {
                #pragma unroll
                for (int it = 0; it < 4; it++) {
                    int f = tid + it * 256;
                    pfa[it] = ldg_pol4(A + (size_t)(m0 + (f >> 3)) * SQ + k0 + 32 + (f & 7) * 4, pef);
                }
                #pragma unroll
                for (int it = 0; it < 2; it++) {
                    int f = tid + it * 256;
                    pfb[it] = *(const float4*)(Bv + (size_t)(k0 + 32 + (f >> 4)) * DK + (f & 15) * 4);
                }
            }

            #pragma unroll
            for (int ks = 0; ks < 4; ks++) {
                int kk = ks * 8;
                u32 a[2][4], bf[4][2];
                #pragma unroll
                for (int mi = 0; mi < 2; mi++) {
                    int r = wm * 32 + mi * 16 + rq;
                    a[mi][0] = As[r][kk + cq];
                    a[mi][1] = As[r + 8][kk + cq];
                    a[mi][2] = As[r][kk + cq + 4];
                    a[mi][3] = As[r + 8][kk + cq + 4];
                }
                #pragma unroll
                for (int ni = 0; ni < 4; ni++) {
                    int n = wn * 32 + ni * 8 + rq;
                    bf[ni][0] = Bs[kk + cq][n];
                    bf[ni][1] = Bs[kk + cq + 4][n];
                }
                #pragma unroll
                for (int mi = 0; mi < 2; mi++)
                    #pragma unroll
                    for (int ni = 0; ni < 4; ni++)
                        mma_tf32(acc[mi][ni], a[mi], bf[ni]);
            }
        }

        #pragma unroll
        for (int mi = 0; mi < 2; mi++) {
            #pragma unroll
            for (int ni = 0; ni < 4; ni++) {
                int r0 = m0 + wm * 32 + mi * 16 + rq;
                int c0 = wn * 32 + ni * 8 + cq * 2;
                float* dst0 = outp + (size_t)(b * SQ + r0) * DM + h * DK + c0;
                float* dst1 = outp + (size_t)(b * SQ + r0 + 8) * DM + h * DK + c0;
                *(float2*)dst0 = make_float2(acc[mi][ni][0], acc[mi][ni][1]);
                *(float2*)dst1 = make_float2(acc[mi][ni][2], acc[mi][ni][3]);
            }
        }
    }
}

// =====================================================================
// K7: out = (g_attn + g_attn2 + g_attn3) @ Wo + bo via tf32 mma.
// attn loads evict_first. BM=64, BN=64, BK=32. grid (32, 12).
// =====================================================================
__global__ __launch_bounds__(256) void k_out(
    const float* __restrict__ Wo, const float* __restrict__ bo, float* __restrict__ out)
{
    __shared__ __align__(16) u32 As[64][36];
    __shared__ __align__(16) u32 Bs[32][72];

    const u64 pef = pol_evict_first();

    const int tid = threadIdx.x;
    const int lane = tid & 31;
    const int warp = tid >> 5;
    const int wm = warp >> 1;    // 0..3 -> m offset *16
    const int wn = warp & 1;     // 0..1 -> n offset *32
    const int rq = lane >> 2;
    const int cq = lane & 3;
    const int m0 = blockIdx.x * 64;
    const int n0 = blockIdx.y * 64;

    float acc[4][4];
    #pragma unroll
    for (int j = 0; j < 4; j++)
        #pragma unroll
        for (int t = 0; t < 4; t++) acc[j][t] = 0.f;

    float4 pfa[2], pfb[2];
    #pragma unroll
    for (int it = 0; it < 2; it++) {
        int f = tid + it * 256;
        size_t idx = (size_t)(m0 + (f >> 3)) * DM + (f & 7) * 4;
        float4 a1 = ldg_pol4(g_attn + idx, pef);
        float4 a2 = ldg_pol4(g_attn2 + idx, pef);
        float4 a3 = ldg_pol4(g_attn3 + idx, pef);
        pfa[it] = make_float4(a1.x + a2.x + a3.x, a1.y + a2.y + a3.y,
                              a1.z + a2.z + a3.z, a1.w + a2.w + a3.w);
        pfb[it] = *(const float4*)(Wo + (size_t)(f >> 4) * DM + n0 + (f & 15) * 4);
    }

    for (int k0 = 0; k0 < DM; k0 += 32) {
        __syncthreads();
        #pragma unroll
        for (int it = 0; it < 2; it++) {
            int f = tid + it * 256;
            *(uint4*)&As[f >> 3][(f & 7) * 4] = cvt4(pfa[it]);
            *(uint4*)&Bs[f >> 4][(f & 15) * 4] = cvt4(pfb[it]);
        }
        __syncthreads();

        if (k0 + 32 < DM) {
            #pragma unroll
            for (int it = 0; it < 2; it++) {
                int f = tid + it * 256;
                size_t idx = (size_t)(m0 + (f >> 3)) * DM + k0 + 32 + (f & 7) * 4;
                float4 a1 = ldg_pol4(g_attn + idx, pef);
                float4 a2 = ldg_pol4(g_attn2 + idx, pef);
                float4 a3 = ldg_pol4(g_attn3 + idx, pef);
                pfa[it] = make_float4(a1.x + a2.x + a3.x, a1.y + a2.y + a3.y,
                                      a1.z + a2.z + a3.z, a1.w + a2.w + a3.w);
                pfb[it] = *(const float4*)(Wo + (size_t)(k0 + 32 + (f >> 4)) * DM + n0 + (f & 15) * 4);
            }
        }

        #pragma unroll
        for (int ks = 0; ks < 4; ks++) {
            int kk = ks * 8;
            u32 a[4], bf[4][2];
            int r = wm * 16 + rq;
            a[0] = As[r][kk + cq];
            a[1] = As[r + 8][kk + cq];
            a[2] = As[r][kk + cq + 4];
            a[3] = As[r + 8][kk + cq + 4];
            #pragma unroll
            for (int ni = 0; ni < 4; ni++) {
                int n = wn * 32 + ni * 8 + rq;
                bf[ni][0] = Bs[kk + cq][n];
                bf[ni][1] = Bs[kk + cq + 4][n];
            }
            #pragma unroll
            for (int ni = 0; ni < 4; ni++)
                mma_tf32(acc[ni], a, bf[ni]);
        }
    }

    #pragma unroll
    for (int ni = 0; ni < 4; ni++) {
        int ncol = wn * 32 + ni * 8 + cq * 2;
        float bx = bo[n0 + ncol];
        float by = bo[n0 + ncol + 1];
        int m = m0 + wm * 16 + rq;
        *(float2*)(out + (size_t)m * DM + n0 + ncol) =
            make_float2(acc[ni][0] + bx, acc[ni][1] + by);
        *(float2*)(out + (size_t)(m + 8) * DM + n0 + ncol) =
            make_float2(acc[ni][2] + bx, acc[ni][3] + by);
    }
}

// =====================================================================
extern "C" void kernel_launch(void* const* d_in, const int* in_sizes, int n_in,
                              void* d_out, int out_size)
{
    const float* queries = (const float*)d_in[0];
    const float* keys    = (const float*)d_in[1];
    const float* values  = (const float*)d_in[2];
    const float* relk    = (const float*)d_in[3];
    const float* relv    = (const float*)d_in[4];
    const float* Wq = (const float*)d_in[5];
    const float* bq = (const float*)d_in[6];
    const float* Wk = (const float*)d_in[7];
    const float* bk = (const float*)d_in[8];
    const float* Wv = (const float*)d_in[9];
    const float* bv = (const float*)d_in[10];
    const float* Wo = (const float*)d_in[11];
    const float* bo = (const float*)d_in[12];
    float* out = (float*)d_out;

    const int qrel_smem = NH * SQ * (int)sizeof(float)
                        + 128 * 68 * (int)sizeof(u32)
                        + 16 * 64 * (int)sizeof(u32);
    const int pv_smem = (128 * 72 + 16 * 132) * (int)sizeof(u32);  // 45312 B

    static bool attr_set = false;
    if (!attr_set) {
        cudaFuncSetAttribute(k_qk, cudaFuncAttributeMaxDynamicSharedMemorySize,
                             2 * 128 * 68 * (int)sizeof(u32));
        cudaFuncSetAttribute(k_qrel_sm, cudaFuncAttributeMaxDynamicSharedMemorySize,
                             qrel_smem);
        cudaFuncSetAttribute(k_pv, cudaFuncAttributeMaxDynamicSharedMemorySize,
                             pv_smem);
        attr_set = true;
    }

    k_proj<<<dim3(16, 12, 3), 256>>>(queries, keys, values, Wq, Wk, Wv, bq, bk, bv);
    k_qk<<<dim3(8, 8, NB * NH), 256, 2 * 128 * 68 * sizeof(u32)>>>();
    k_qrel_sm<<<dim3(SQ, NB), 512, qrel_smem>>>(relk);
    k_pv<<<dim3(2048 + 8 * NB * NH * 2), 256, pv_smem>>>(relv);
    k_out<<<dim3(32, 12), 256>>>(Wo, bo, out);
}

// round 15
// speedup vs baseline: 1.1647x; 1.1647x over previous
#include <cuda_runtime.h>

typedef unsigned long long u64;
typedef unsigned int u32;

#define NB 2
#define NH 12
#define SQ 1024
#define DK 64
#define DM 768

// ---------------- scratch ----------------
__device__ float g_q[NB*NH*SQ*DK];                 // pre-scaled by 1/64
__device__ float g_k[NB*NH*SQ*DK];
__device__ float g_v[NB*NH*SQ*DK];
__device__ float g_scores[(size_t)NB*NH*SQ*SQ];    // scores, then probs (in place)
__device__ float g_attn[NB*SQ*DM];                 // w_rel
__device__ float g_attn2[NB*SQ*DM];                // wv partial (k 0..511)
__device__ float g_attn3[NB*SQ*DM];                // wv partial (k 512..1023)

// ---------------- tf32 mma helpers ----------------
__device__ __forceinline__ u32 to_tf32(float f){
    u32 u; asm("cvt.rna.tf32.f32 %0, %1;" : "=r"(u) : "f"(f)); return u;
}
__device__ __forceinline__ uint4 cvt4(float4 v){
    uint4 u; u.x = to_tf32(v.x); u.y = to_tf32(v.y); u.z = to_tf32(v.z); u.w = to_tf32(v.w);
    return u;
}
__device__ __forceinline__ void mma_tf32(float* c, const u32* a, const u32* b){
    asm volatile(
        "mma.sync.aligned.m16n8k8.row.col.f32.tf32.tf32.f32 "
        "{%0,%1,%2,%3}, {%4,%5,%6,%7}, {%8,%9}, {%0,%1,%2,%3};"
        : "+f"(c[0]), "+f"(c[1]), "+f"(c[2]), "+f"(c[3])
        : "r"(a[0]), "r"(a[1]), "r"(a[2]), "r"(a[3]), "r"(b[0]), "r"(b[1]));
}

// =====================================================================
// K1: QKV projections via tf32 mma (plain tf32, single mma).
// BM=128, BN=64 (one head), BK=32. grid (16, 12, 3).
// =====================================================================
__global__ __launch_bounds__(256) void k_proj(
    const float* __restrict__ Xq, const float* __restrict__ Xk, const float* __restrict__ Xv,
    const float* __restrict__ Wq, const float* __restrict__ Wk, const float* __restrict__ Wv,
    const float* __restrict__ bq, const float* __restrict__ bk, const float* __restrict__ bv)
{
    const int z = blockIdx.z;
    const float* X    = (z == 0) ? Xq : (z == 1) ? Xk : Xv;
    const float* W    = (z == 0) ? Wq : (z == 1) ? Wk : Wv;
    const float* bias = (z == 0) ? bq : (z == 1) ? bk : bv;
    float* out        = (z == 0) ? g_q : (z == 1) ? g_k : g_v;
    const float scale = (z == 0) ? (1.0f / 64.0f) : 1.0f;

    __shared__ __align__(16) u32 As[128][36];
    __shared__ __align__(16) u32 Bs[32][72];

    const int tid = threadIdx.x;
    const int lane = tid & 31;
    const int warp = tid >> 5;
    const int wm = warp >> 1;
    const int wn = warp & 1;
    const int rq = lane >> 2;
    const int cq = lane & 3;
    const int m0 = blockIdx.x * 128;
    const int h  = blockIdx.y;
    const int n0 = h * 64;

    float acc[2][4][4];
    #pragma unroll
    for (int i = 0; i < 2; i++)
        #pragma unroll
        for (int j = 0; j < 4; j++)
            #pragma unroll
            for (int t = 0; t < 4; t++) acc[i][j][t] = 0.f;

    float4 pfa[4], pfb[2];
    #pragma unroll
    for (int it = 0; it < 4; it++) {
        int f = tid + it * 256;
        pfa[it] = *(const float4*)(X + (size_t)(m0 + (f >> 3)) * DM + (f & 7) * 4);
    }
    #pragma unroll
    for (int it = 0; it < 2; it++) {
        int f = tid + it * 256;
        pfb[it] = *(const float4*)(W + (size_t)(f >> 4) * DM + n0 + (f & 15) * 4);
    }

    for (int k0 = 0; k0 < DM; k0 += 32) {
        __syncthreads();
        #pragma unroll
        for (int it = 0; it < 4; it++) {
            int f = tid + it * 256;
            *(uint4*)&As[f >> 3][(f & 7) * 4] = cvt4(pfa[it]);
        }
        #pragma unroll
        for (int it = 0; it < 2; it++) {
            int f = tid + it * 256;
            *(uint4*)&Bs[f >> 4][(f & 15) * 4] = cvt4(pfb[it]);
        }
        __syncthreads();

        if (k0 + 32 < DM) {
            #pragma unroll
            for (int it = 0; it < 4; it++) {
                int f = tid + it * 256;
                pfa[it] = *(const float4*)(X + (size_t)(m0 + (f >> 3)) * DM + k0 + 32 + (f & 7) * 4);
            }
            #pragma unroll
            for (int it = 0; it < 2; it++) {
                int f = tid + it * 256;
                pfb[it] = *(const float4*)(W + (size_t)(k0 + 32 + (f >> 4)) * DM + n0 + (f & 15) * 4);
            }
        }

        #pragma unroll
        for (int ks = 0; ks < 4; ks++) {
            int kk = ks * 8;
            u32 a[2][4], bf[4][2];
            #pragma unroll
            for (int mi = 0; mi < 2; mi++) {
                int r = wm * 32 + mi * 16 + rq;
                a[mi][0] = As[r][kk + cq];
                a[mi][1] = As[r + 8][kk + cq];
                a[mi][2] = As[r][kk + cq + 4];
                a[mi][3] = As[r + 8][kk + cq + 4];
            }
            #pragma unroll
            for (int ni = 0; ni < 4; ni++) {
                int n = wn * 32 + ni * 8 + rq;
                bf[ni][0] = Bs[kk + cq][n];
                bf[ni][1] = Bs[kk + cq + 4][n];
            }
            #pragma unroll
            for (int mi = 0; mi < 2; mi++)
                #pragma unroll
                for (int ni = 0; ni < 4; ni++)
                    mma_tf32(acc[mi][ni], a[mi], bf[ni]);
        }
    }

    #pragma unroll
    for (int mi = 0; mi < 2; mi++) {
        #pragma unroll
        for (int ni = 0; ni < 4; ni++) {
            int ncol = wn * 32 + ni * 8 + cq * 2;
            float bx = bias[n0 + ncol];
            float by = bias[n0 + ncol + 1];
            int m = m0 + wm * 32 + mi * 16 + rq;
            {
                int b = m >> 10, s = m & (SQ - 1);
                float* dst = out + ((size_t)((b * NH + h) * SQ + s)) * DK + ncol;
                *(float2*)dst = make_float2((acc[mi][ni][0] + bx) * scale,
                                            (acc[mi][ni][1] + by) * scale);
            }
            {
                int m2 = m + 8;
                int b = m2 >> 10, s = m2 & (SQ - 1);
                float* dst = out + ((size_t)((b * NH + h) * SQ + s)) * DK + ncol;
                *(float2*)dst = make_float2((acc[mi][ni][2] + bx) * scale,
                                            (acc[mi][ni][3] + by) * scale);
            }
        }
    }
}

// =====================================================================
// K2: scores = q @ k^T per (b,h) via tf32 mma. CTA tile 128x128.
// grid (8, 8, 24), dyn smem 69632 B.
// =====================================================================
__global__ __launch_bounds__(256) void k_qk()
{
    extern __shared__ __align__(16) u32 smu[];
    u32 (*Qs)[68] = (u32(*)[68])smu;
    u32 (*Ks)[68] = (u32(*)[68])(smu + 128 * 68);

    const int bh = blockIdx.z;
    const float* Aq = g_q + (size_t)bh * SQ * DK;
    const float* Bk = g_k + (size_t)bh * SQ * DK;
    float* C = g_scores + (size_t)bh * SQ * SQ;

    const int m0 = blockIdx.x * 128;
    const int n0 = blockIdx.y * 128;
    const int tid = threadIdx.x;
    const int lane = tid & 31;
    const int warp = tid >> 5;
    const int wm = warp >> 2;
    const int wn = warp & 3;
    const int rq = lane >> 2;
    const int cq = lane & 3;

    #pragma unroll
    for (int it = 0; it < 8; it++) {
        int f = tid + it * 256;
        int r  = f >> 4;
        int d4 = (f & 15) * 4;
        float4 va = *(const float4*)(Aq + (size_t)(m0 + r) * DK + d4);
        float4 vb = *(const float4*)(Bk + (size_t)(n0 + r) * DK + d4);
        *(uint4*)&Qs[r][d4] = cvt4(va);
        *(uint4*)&Ks[r][d4] = cvt4(vb);
    }
    __syncthreads();

    float acc[4][4][4];
    #pragma unroll
    for (int i = 0; i < 4; i++)
        #pragma unroll
        for (int j = 0; j < 4; j++)
            #pragma unroll
            for (int t = 0; t < 4; t++) acc[i][j][t] = 0.f;

    #pragma unroll
    for (int ks = 0; ks < 8; ks++) {
        int d0 = ks * 8;
        u32 a[4][4], bf[4][2];
        #pragma unroll
        for (int mi = 0; mi < 4; mi++) {
            int r = wm * 64 + mi * 16 + rq;
            a[mi][0] = Qs[r][d0 + cq];
            a[mi][1] = Qs[r + 8][d0 + cq];
            a[mi][2] = Qs[r][d0 + cq + 4];
            a[mi][3] = Qs[r + 8][d0 + cq + 4];
        }
        #pragma unroll
        for (int ni = 0; ni < 4; ni++) {
            int n = wn * 32 + ni * 8 + rq;
            bf[ni][0] = Ks[n][d0 + cq];
            bf[ni][1] = Ks[n][d0 + cq + 4];
        }
        #pragma unroll
        for (int mi = 0; mi < 4; mi++)
            #pragma unroll
            for (int ni = 0; ni < 4; ni++)
                mma_tf32(acc[mi][ni], a[mi], bf[ni]);
    }

    #pragma unroll
    for (int mi = 0; mi < 4; mi++) {
        #pragma unroll
        for (int ni = 0; ni < 4; ni++) {
            int r0 = m0 + wm * 64 + mi * 16 + rq;
            int c0 = n0 + wn * 32 + ni * 8 + cq * 2;
            *(float2*)(C + (size_t)r0 * SQ + c0)       = make_float2(acc[mi][ni][0], acc[mi][ni][1]);
            *(float2*)(C + (size_t)(r0 + 8) * SQ + c0) = make_float2(acc[mi][ni][2], acc[mi][ni][3]);
        }
    }
}

// =====================================================================
// K3 (fused): per (b,q): scores += q . relation_k (tf32 mma), softmax.
// 512 threads = 16 warps. grid (1024, 2), dyn smem 88064 B.
// =====================================================================
__global__ __launch_bounds__(512) void k_qrel_sm(const float* __restrict__ relk)
{
    extern __shared__ __align__(16) float sm[];
    float* ss = sm;                                        // 12*1024 floats
    u32 (*rks)[68] = (u32(*)[68])(sm + NH * SQ);           // 128*68 tf32
    u32 (*qs)[64] = (u32(*)[64])(sm + NH * SQ + 128 * 68); // 16*64 tf32 (rows 12-15 zero)

    const int b = blockIdx.y, q = blockIdx.x;
    const int tid = threadIdx.x;
    const int lane = tid & 31;
    const int warp = tid >> 5;       // 0..15
    const int rq = lane >> 2;        // 0..7
    const int cq = lane & 3;         // 0..3
    const int n0c = warp * 8;

    if (tid < 192) {
        int hh = tid >> 4;
        int d4 = (tid & 15) * 4;
        float4 v = *(const float4*)(g_q + ((size_t)((b * NH + hh) * SQ + q)) * DK + d4);
        *(uint4*)&qs[hh][d4] = cvt4(v);
    } else if (tid < 256) {
        int r = 12 + ((tid - 192) >> 4);
        int d4 = ((tid - 192) & 15) * 4;
        *(uint4*)&qs[r][d4] = make_uint4(0u, 0u, 0u, 0u);
    }
    #pragma unroll
    for (int it = 0; it < 6; it++) {
        int f = tid + it * 512;
        int hh = f >> 8;
        int k4 = (f & 255) * 4;
        *(float4*)&ss[hh * SQ + k4] =
            *(const float4*)(g_scores + ((size_t)((b * NH + hh) * SQ + q)) * SQ + k4);
    }

    const float* relbase = relk + ((size_t)(b * SQ + q)) * SQ * DK;

    float4 pf[4];
    #pragma unroll
    for (int it = 0; it < 4; it++) {
        int f = tid + it * 512;
        pf[it] = *(const float4*)(relbase + (size_t)(f >> 4) * DK + (f & 15) * 4);
    }
    __syncthreads();

    u32 afrag[8][4];
    #pragma unroll
    for (int ks = 0; ks < 8; ks++) {
        int d0 = ks * 8;
        afrag[ks][0] = qs[rq][d0 + cq];
        afrag[ks][1] = qs[rq + 8][d0 + cq];
        afrag[ks][2] = qs[rq][d0 + cq + 4];
        afrag[ks][3] = qs[rq + 8][d0 + cq + 4];
    }

    for (int kt = 0; kt < SQ; kt += 128) {
        __syncthreads();
        #pragma unroll
        for (int it = 0; it < 4; it++) {
            int f = tid + it * 512;
            *(uint4*)&rks[f >> 4][(f & 15) * 4] = cvt4(pf[it]);
        }
        __syncthreads();

        if (kt + 128 < SQ) {
            #pragma unroll
            for (int it = 0; it < 4; it++) {
                int f = tid + it * 512;
                pf[it] = *(const float4*)(relbase + (size_t)(kt + 128 + (f >> 4)) * DK + (f & 15) * 4);
            }
        }

        float acc[4] = {0.f, 0.f, 0.f, 0.f};
        #pragma unroll
        for (int ks = 0; ks < 8; ks++) {
            int d0 = ks * 8;
            u32 bf[2];
            bf[0] = rks[n0c + rq][d0 + cq];
            bf[1] = rks[n0c + rq][d0 + cq + 4];
            mma_tf32(acc, afrag[ks], bf);
        }

        int col = kt + n0c + cq * 2;
        ss[rq * SQ + col]     += acc[0];
        ss[rq * SQ + col + 1] += acc[1];
        if (rq < 4) {
            ss[(rq + 8) * SQ + col]     += acc[2];
            ss[(rq + 8) * SQ + col + 1] += acc[3];
        }
    }
    __syncthreads();

    const int swarp = tid >> 5;
    const int slane = tid & 31;
    if (swarp < NH) {
        float* p = ss + swarp * SQ;
        float4 v[8];
        float mx = -3.4e38f;
        #pragma unroll
        for (int j = 0; j < 8; j++) {
            v[j] = *(float4*)(p + slane * 4 + j * 128);
            mx = fmaxf(mx, fmaxf(fmaxf(v[j].x, v[j].y), fmaxf(v[j].z, v[j].w)));
        }
        #pragma unroll
        for (int o = 16; o > 0; o >>= 1) mx = fmaxf(mx, __shfl_xor_sync(0xffffffffu, mx, o));

        float s = 0.f;
        #pragma unroll
        for (int j = 0; j < 8; j++) {
            v[j].x = __expf(v[j].x - mx);
            v[j].y = __expf(v[j].y - mx);
            v[j].z = __expf(v[j].z - mx);
            v[j].w = __expf(v[j].w - mx);
            s += v[j].x + v[j].y + v[j].z + v[j].w;
        }
        #pragma unroll
        for (int o = 16; o > 0; o >>= 1) s += __shfl_xor_sync(0xffffffffu, s, o);
        const float inv = 1.0f / s;

        float* dst = g_scores + ((size_t)((b * NH + swarp) * SQ + q)) * SQ;
        #pragma unroll
        for (int j = 0; j < 8; j++) {
            v[j].x *= inv; v[j].y *= inv; v[j].z *= inv; v[j].w *= inv;
            *(float4*)(dst + slane * 4 + j * 128) = v[j];
        }
    }
}

// =====================================================================
// K5+K6 merged (k_pv): single launch, flattened grid of 2432 CTAs.
//   CTAs [0, 2048): w_rel  = probs @ relation_v  -> g_attn
//   CTAs [2048, 2432): wv  = probs @ v (split-K) -> g_attn2/g_attn3
// 256 threads, dyn smem 45312 B.
// =====================================================================
__global__ __launch_bounds__(256) void k_pv(const float* __restrict__ relv)
{
    extern __shared__ __align__(16) u32 dyn[];

    const int tid = threadIdx.x;
    const int lane = tid & 31;
    const int warp = tid >> 5;
    const int rq = lane >> 2;
    const int cq = lane & 3;

    if (blockIdx.x < 2048) {
        // ---------------- w_rel path ----------------
        u32 (*rvs)[72] = (u32(*)[72])dyn;                 // 128x72
        u32 (*ps)[132] = (u32(*)[132])(dyn + 128 * 72);   // 16x132

        const int q = blockIdx.x & (SQ - 1);
        const int b = blockIdx.x >> 10;
        const int n0c = warp * 8;

        {
            int r = 12 + (tid >> 6);
            int c = (tid & 63) * 2;
            ps[r][c] = 0u; ps[r][c + 1] = 0u;
        }

        const float* relbase = relv + ((size_t)(b * SQ + q)) * SQ * DK;
        const float* psrc = g_scores + ((size_t)(b * NH) * SQ + q) * SQ;

        float acc[4] = {0.f, 0.f, 0.f, 0.f};

        float4 pfr[8], pfp[2];
        #pragma unroll
        for (int it = 0; it < 8; it++) {
            int f = tid + it * 256;
            pfr[it] = *(const float4*)(relbase + (size_t)(f >> 4) * DK + (f & 15) * 4);
        }
        #pragma unroll
        for (int it = 0; it < 2; it++) {
            int f = tid + it * 256;
            if (f < 384)
                pfp[it] = *(const float4*)(psrc + (size_t)(f >> 5) * SQ * SQ + (f & 31) * 4);
        }

        for (int kt = 0; kt < SQ; kt += 128) {
            __syncthreads();
            #pragma unroll
            for (int it = 0; it < 8; it++) {
                int f = tid + it * 256;
                *(uint4*)&rvs[f >> 4][(f & 15) * 4] = cvt4(pfr[it]);
            }
            #pragma unroll
            for (int it = 0; it < 2; it++) {
                int f = tid + it * 256;
                if (f < 384)
                    *(uint4*)&ps[f >> 5][(f & 31) * 4] = cvt4(pfp[it]);
            }
            __syncthreads();

            if (kt + 128 < SQ) {
                #pragma unroll
                for (int it = 0; it < 8; it++) {
                    int f = tid + it * 256;
                    pfr[it] = *(const float4*)(relbase + (size_t)(kt + 128 + (f >> 4)) * DK + (f & 15) * 4);
                }
                #pragma unroll
                for (int it = 0; it < 2; it++) {
                    int f = tid + it * 256;
                    if (f < 384)
                        pfp[it] = *(const float4*)(psrc + (size_t)(f >> 5) * SQ * SQ + kt + 128 + (f & 31) * 4);
                }
            }

            #pragma unroll
            for (int ks = 0; ks < 16; ks++) {
                int kk = ks * 8;
                u32 a[4], bf[2];
                a[0] = ps[rq][kk + cq];
                a[1] = ps[rq + 8][kk + cq];
                a[2] = ps[rq][kk + cq + 4];
                a[3] = ps[rq + 8][kk + cq + 4];
                bf[0] = rvs[kk + cq][n0c + rq];
                bf[1] = rvs[kk + cq + 4][n0c + rq];
                mma_tf32(acc, a, bf);
            }
        }

        const size_t base = (size_t)(b * SQ + q) * DM;
        const int col = n0c + cq * 2;
        *(float2*)(g_attn + base + rq * DK + col) = make_float2(acc[0], acc[1]);
        if (rq < 4)
            *(float2*)(g_attn + base + (rq + 8) * DK + col) = make_float2(acc[2], acc[3]);
    } else {
        // ---------------- wv path ----------------
        u32 (*As)[36] = (u32(*)[36])dyn;                 // 128x36
        u32 (*Bs)[72] = (u32(*)[72])(dyn + 128 * 36);    // 32x72

        const int idx = blockIdx.x - 2048;
        const int m0 = (idx & 7) * 128;
        const int bh = (idx >> 3) % (NB * NH);
        const int kz = idx / (8 * NB * NH);
        const int b = bh / NH, h = bh % NH;
        const int koff = kz * 512;
        const float* A  = g_scores + (size_t)bh * SQ * SQ + koff;
        const float* Bv = g_v + ((size_t)bh * SQ + koff) * DK;
        float* outp = kz ? g_attn3 : g_attn2;

        const int wm = warp >> 1;
        const int wn = warp & 1;

        float acc[2][4][4];
        #pragma unroll
        for (int i = 0; i < 2; i++)
            #pragma unroll
            for (int j = 0; j < 4; j++)
                #pragma unroll
                for (int t = 0; t < 4; t++) acc[i][j][t] = 0.f;

        float4 pfa[4], pfb[2];
        #pragma unroll
        for (int it = 0; it < 4; it++) {
            int f = tid + it * 256;
            pfa[it] = *(const float4*)(A + (size_t)(m0 + (f >> 3)) * SQ + (f & 7) * 4);
        }
        #pragma unroll
        for (int it = 0; it < 2; it++) {
            int f = tid + it * 256;
            pfb[it] = *(const float4*)(Bv + (size_t)(f >> 4) * DK + (f & 15) * 4);
        }

        for (int k0 = 0; k0 < 512; k0 += 32) {
            __syncthreads();
            #pragma unroll
            for (int it = 0; it < 4; it++) {
                int f = tid + it * 256;
                *(uint4*)&As[f >> 3][(f & 7) * 4] = cvt4(pfa[it]);
            }
            #pragma unroll
            for (int it = 0; it < 2; it++) {
                int f = tid + it * 256;
                *(uint4*)&Bs[f >> 4][(f & 15) * 4] = cvt4(pfb[it]);
            }
            __syncthreads();

            if (k0 + 32 < 512) {
                #pragma unroll
                for (int it = 0; it < 4; it++) {
                    int f = tid + it * 256;
                    pfa[it] = *(const float4*)(A + (size_t)(m0 + (f >> 3)) * SQ + k0 + 32 + (f & 7) * 4);
                }
                #pragma unroll
                for (int it = 0; it < 2; it++) {
                    int f = tid + it * 256;
                    pfb[it] = *(const float4*)(Bv + (size_t)(k0 + 32 + (f >> 4)) * DK + (f & 15) * 4);
                }
            }

            #pragma unroll
            for (int ks = 0; ks < 4; ks++) {
                int kk = ks * 8;
                u32 a[2][4], bf[4][2];
                #pragma unroll
                for (int mi = 0; mi < 2; mi++) {
                    int r = wm * 32 + mi * 16 + rq;
                    a[mi][0] = As[r][kk + cq];
                    a[mi][1] = As[r + 8][kk + cq];
                    a[mi][2] = As[r][kk + cq + 4];
                    a[mi][3] = As[r + 8][kk + cq + 4];
                }
                #pragma unroll
                for (int ni = 0; ni < 4; ni++) {
                    int n = wn * 32 + ni * 8 + rq;
                    bf[ni][0] = Bs[kk + cq][n];
                    bf[ni][1] = Bs[kk + cq + 4][n];
                }
                #pragma unroll
                for (int mi = 0; mi < 2; mi++)
                    #pragma unroll
                    for (int ni = 0; ni < 4; ni++)
                        mma_tf32(acc[mi][ni], a[mi], bf[ni]);
            }
        }

        #pragma unroll
        for (int mi = 0; mi < 2; mi++) {
            #pragma unroll
            for (int ni = 0; ni < 4; ni++) {
                int r0 = m0 + wm * 32 + mi * 16 + rq;
                int c0 = wn * 32 + ni * 8 + cq * 2;
                float* dst0 = outp + (size_t)(b * SQ + r0) * DM + h * DK + c0;
                float* dst1 = outp + (size_t)(b * SQ + r0 + 8) * DM + h * DK + c0;
                *(float2*)dst0 = make_float2(acc[mi][ni][0], acc[mi][ni][1]);
                *(float2*)dst1 = make_float2(acc[mi][ni][2], acc[mi][ni][3]);
            }
        }
    }
}

// =====================================================================
// K7: out = (g_attn + g_attn2 + g_attn3) @ Wo + bo via tf32 mma.
// BM=64, BN=64, BK=32. grid (32, 12).
// =====================================================================
__global__ __launch_bounds__(256) void k_out(
    const float* __restrict__ Wo, const float* __restrict__ bo, float* __restrict__ out)
{
    __shared__ __align__(16) u32 As[64][36];
    __shared__ __align__(16) u32 Bs[32][72];

    const int tid = threadIdx.x;
    const int lane = tid & 31;
    const int warp = tid >> 5;
    const int wm = warp >> 1;    // 0..3 -> m offset *16
    const int wn = warp & 1;     // 0..1 -> n offset *32
    const int rq = lane >> 2;
    const int cq = lane & 3;
    const int m0 = blockIdx.x * 64;
    const int n0 = blockIdx.y * 64;

    float acc[4][4];
    #pragma unroll
    for (int j = 0; j < 4; j++)
        #pragma unroll
        for (int t = 0; t < 4; t++) acc[j][t] = 0.f;

    float4 pfa[2], pfb[2];
    #pragma unroll
    for (int it = 0; it < 2; it++) {
        int f = tid + it * 256;
        size_t idx = (size_t)(m0 + (f >> 3)) * DM + (f & 7) * 4;
        float4 a1 = *(const float4*)(g_attn + idx);
        float4 a2 = *(const float4*)(g_attn2 + idx);
        float4 a3 = *(const float4*)(g_attn3 + idx);
        pfa[it] = make_float4(a1.x + a2.x + a3.x, a1.y + a2.y + a3.y,
                              a1.z + a2.z + a3.z, a1.w + a2.w + a3.w);
        pfb[it] = *(const float4*)(Wo + (size_t)(f >> 4) * DM + n0 + (f & 15) * 4);
    }

    for (int k0 = 0; k0 < DM; k0 += 32) {
        __syncthreads();
        #pragma unroll
        for (int it = 0; it < 2; it++) {
            int f = tid + it * 256;
            *(uint4*)&As[f >> 3][(f & 7) * 4] = cvt4(pfa[it]);
            *(uint4*)&Bs[f >> 4][(f & 15) * 4] = cvt4(pfb[it]);
        }
        __syncthreads();

        if (k0 + 32 < DM) {
            #pragma unroll
            for (int it = 0; it < 2; it++) {
                int f = tid + it * 256;
                size_t idx = (size_t)(m0 + (f >> 3)) * DM + k0 + 32 + (f & 7) * 4;
                float4 a1 = *(const float4*)(g_attn + idx);
                float4 a2 = *(const float4*)(g_attn2 + idx);
                float4 a3 = *(const float4*)(g_attn3 + idx);
                pfa[it] = make_float4(a1.x + a2.x + a3.x, a1.y + a2.y + a3.y,
                                      a1.z + a2.z + a3.z, a1.w + a2.w + a3.w);
                pfb[it] = *(const float4*)(Wo + (size_t)(k0 + 32 + (f >> 4)) * DM + n0 + (f & 15) * 4);
            }
        }

        #pragma unroll
        for (int ks = 0; ks < 4; ks++) {
            int kk = ks * 8;
            u32 a[4], bf[4][2];
            int r = wm * 16 + rq;
            a[0] = As[r][kk + cq];
            a[1] = As[r + 8][kk + cq];
            a[2] = As[r][kk + cq + 4];
            a[3] = As[r + 8][kk + cq + 4];
            #pragma unroll
            for (int ni = 0; ni < 4; ni++) {
                int n = wn * 32 + ni * 8 + rq;
                bf[ni][0] = Bs[kk + cq][n];
                bf[ni][1] = Bs[kk + cq + 4][n];
            }
            #pragma unroll
            for (int ni = 0; ni < 4; ni++)
                mma_tf32(acc[ni], a, bf[ni]);
        }
    }

    #pragma unroll
    for (int ni = 0; ni < 4; ni++) {
        int ncol = wn * 32 + ni * 8 + cq * 2;
        float bx = bo[n0 + ncol];
        float by = bo[n0 + ncol + 1];
        int m = m0 + wm * 16 + rq;
        *(float2*)(out + (size_t)m * DM + n0 + ncol) =
            make_float2(acc[ni][0] + bx, acc[ni][1] + by);
        *(float2*)(out + (size_t)(m + 8) * DM + n0 + ncol) =
            make_float2(acc[ni][2] + bx, acc[ni][3] + by);
    }
}

// =====================================================================
extern "C" void kernel_launch(void* const* d_in, const int* in_sizes, int n_in,
                              void* d_out, int out_size)
{
    const float* queries = (const float*)d_in[0];
    const float* keys    = (const float*)d_in[1];
    const float* values  = (const float*)d_in[2];
    const float* relk    = (const float*)d_in[3];
    const float* relv    = (const float*)d_in[4];
    const float* Wq = (const float*)d_in[5];
    const float* bq = (const float*)d_in[6];
    const float* Wk = (const float*)d_in[7];
    const float* bk = (const float*)d_in[8];
    const float* Wv = (const float*)d_in[9];
    const float* bv = (const float*)d_in[10];
    const float* Wo = (const float*)d_in[11];
    const float* bo = (const float*)d_in[12];
    float* out = (float*)d_out;

    const int qrel_smem = NH * SQ * (int)sizeof(float)
                        + 128 * 68 * (int)sizeof(u32)
                        + 16 * 64 * (int)sizeof(u32);
    const int pv_smem = (128 * 72 + 16 * 132) * (int)sizeof(u32);  // 45312 B

    static bool attr_set = false;
    if (!attr_set) {
        cudaFuncSetAttribute(k_qk, cudaFuncAttributeMaxDynamicSharedMemorySize,
                             2 * 128 * 68 * (int)sizeof(u32));
        cudaFuncSetAttribute(k_qrel_sm, cudaFuncAttributeMaxDynamicSharedMemorySize,
                             qrel_smem);
        cudaFuncSetAttribute(k_pv, cudaFuncAttributeMaxDynamicSharedMemorySize,
                             pv_smem);
        attr_set = true;
    }

    k_proj<<<dim3(16, 12, 3), 256>>>(queries, keys, values, Wq, Wk, Wv, bq, bk, bv);
    k_qk<<<dim3(8, 8, NB * NH), 256, 2 * 128 * 68 * sizeof(u32)>>>();
    k_qrel_sm<<<dim3(SQ, NB), 512, qrel_smem>>>(relk);
    k_pv<<<dim3(2048 + 8 * NB * NH * 2), 256, pv_smem>>>(relv);
    k_out<<<dim3(32, 12), 256>>>(Wo, bo, out);
}